// round 2
// baseline (speedup 1.0000x reference)
#include <cuda_runtime.h>
#include <math.h>

// Problem constants (fixed by setup_inputs)
#define NN    4096
#define INF_  256
#define SEG   512
#define HALF  64
#define WIN   128
#define NHEAD 4
#define HD    64
#define TOPK  32

// attention kernel tiling
#define NODES_PER_BLK 8
#define MAXROWS 136          // union window rows: (NODES_PER_BLK-1) + 128 = 135, pad to 136
#define KSTR 260             // K smem row stride (floats); 260%32==4 -> conflict-free LDS.128

// scratch: Q||K projections, [4096][512]  (cols 0..255 = Q, 256..511 = K)
__device__ float g_QK[(size_t)NN * 512];

// ---------------------------------------------------------------------------
// zero-fill output (64 MB)
// ---------------------------------------------------------------------------
__global__ void zero_out_kernel(float4* __restrict__ out, int n4) {
    int idx = blockIdx.x * blockDim.x + threadIdx.x;
    int stride = gridDim.x * blockDim.x;
    float4 z = make_float4(0.f, 0.f, 0.f, 0.f);
    for (int i = idx; i < n4; i += stride) out[i] = z;
}

// ---------------------------------------------------------------------------
// fused Q||K projection GEMM:  C[4096,512] = X[4096,256] @ [Wq|Wk] + [bq|bk]
// BM=128, BN=128, BK=16, 256 threads, 8x8 per thread
// ---------------------------------------------------------------------------
__global__ __launch_bounds__(256) void gemm_qk_kernel(
    const float* __restrict__ X,
    const float* __restrict__ Wq, const float* __restrict__ bq,
    const float* __restrict__ Wk, const float* __restrict__ bk)
{
    __shared__ float As[16][128];   // transposed A tile
    __shared__ float Bs[16][128];

    const int tid  = threadIdx.x;
    const int brow = blockIdx.y * 128;
    const int bcol = blockIdx.x * 128;

    // each block lies entirely in the Q half (bcol<256) or K half
    const float* W    = (bcol < 256) ? Wq : Wk;
    const float* bias = (bcol < 256) ? bq : bk;
    const int wcol = bcol & 255;

    const int tx = tid & 15;
    const int ty = tid >> 4;

    float acc[8][8];
#pragma unroll
    for (int a = 0; a < 8; a++)
#pragma unroll
        for (int b = 0; b < 8; b++) acc[a][b] = 0.f;

    for (int k0 = 0; k0 < INF_; k0 += 16) {
        // load A tile 128x16 (512 float4, 2 per thread), transpose into As[k][m]
#pragma unroll
        for (int t = 0; t < 2; t++) {
            int f = tid + t * 256;
            int r = f >> 2;
            int c = (f & 3) << 2;
            float4 v = *(const float4*)(X + (size_t)(brow + r) * INF_ + k0 + c);
            As[c + 0][r] = v.x;
            As[c + 1][r] = v.y;
            As[c + 2][r] = v.z;
            As[c + 3][r] = v.w;
        }
        // load B tile 16x128 (row-major copy)
#pragma unroll
        for (int t = 0; t < 2; t++) {
            int f = tid + t * 256;
            int r = f >> 5;
            int c = (f & 31) << 2;
            *(float4*)&Bs[r][c] =
                *(const float4*)(W + (size_t)(k0 + r) * 256 + wcol + c);
        }
        __syncthreads();

#pragma unroll
        for (int k = 0; k < 16; k++) {
            float a[8], b[8];
            *(float4*)&a[0] = *(float4*)&As[k][ty * 8];
            *(float4*)&a[4] = *(float4*)&As[k][ty * 8 + 4];
            *(float4*)&b[0] = *(float4*)&Bs[k][tx * 8];
            *(float4*)&b[4] = *(float4*)&Bs[k][tx * 8 + 4];
#pragma unroll
            for (int ii = 0; ii < 8; ii++)
#pragma unroll
                for (int jj = 0; jj < 8; jj++)
                    acc[ii][jj] += a[ii] * b[jj];
        }
        __syncthreads();
    }

    // epilogue: +bias, store
#pragma unroll
    for (int ii = 0; ii < 8; ii++) {
        int r = brow + ty * 8 + ii;
#pragma unroll
        for (int jj = 0; jj < 8; jj += 4) {
            int cl = tx * 8 + jj;            // col within block
            float4 v;
            v.x = acc[ii][jj + 0] + bias[wcol + cl + 0];
            v.y = acc[ii][jj + 1] + bias[wcol + cl + 1];
            v.z = acc[ii][jj + 2] + bias[wcol + cl + 2];
            v.w = acc[ii][jj + 3] + bias[wcol + cl + 3];
            *(float4*)(g_QK + (size_t)r * 512 + bcol + cl) = v;
        }
    }
}

// ---------------------------------------------------------------------------
// windowed attention + softmax (with zero-padding in denominator, matching
// the reference which does NOT mask the softmax) + top-32 scatter of 1.0f.
// One warp per node, 8 nodes per block, K window union staged in smem.
// ---------------------------------------------------------------------------
__global__ __launch_bounds__(256) void attn_topk_kernel(float* __restrict__ out)
{
    extern __shared__ float smem[];
    float* Ksm = smem;                       // [MAXROWS][KSTR]
    float* Qsm = smem + MAXROWS * KSTR;      // [8][256]

    const int i0   = blockIdx.x * NODES_PER_BLK;
    const int s0   = i0 & ~(SEG - 1);
    const int e0   = s0 + SEG;
    const int w_lo = max(s0, i0 - HALF);
    const int w_hi = min(e0, i0 + (NODES_PER_BLK - 1) + HALF);
    const int rows = w_hi - w_lo;            // <= 135

    // stage K rows [w_lo, w_hi)
    for (int idx = threadIdx.x; idx < rows * 64; idx += 256) {
        int r = idx >> 6;
        int c = (idx & 63) << 2;
        *(float4*)(Ksm + r * KSTR + c) =
            *(const float4*)(g_QK + (size_t)(w_lo + r) * 512 + 256 + c);
    }
    // stage Q rows i0..i0+7
    for (int idx = threadIdx.x; idx < NODES_PER_BLK * 64; idx += 256) {
        int r = idx >> 6;
        int c = (idx & 63) << 2;
        *(float4*)(Qsm + r * 256 + c) =
            *(const float4*)(g_QK + (size_t)(i0 + r) * 512 + c);
    }
    __syncthreads();

    const int w    = threadIdx.x >> 5;
    const int lane = threadIdx.x & 31;
    const int i    = i0 + w;
    const int start = max(s0, i - HALF);
    const int end   = min(e0, i + HALF);     // exclusive; valid count L in [64,128]

    // scores[q][h] for window slot m = q*32 + lane; invalid slots -> exactly 0
    float sc[4][4];
#pragma unroll
    for (int h = 0; h < NHEAD; h++) {
        float4 qv[16];
#pragma unroll
        for (int d = 0; d < 16; d++)
            qv[d] = *(const float4*)(Qsm + w * 256 + h * HD + d * 4);
#pragma unroll
        for (int q = 0; q < 4; q++) {
            int j = start + q * 32 + lane;
            float a = 0.f;
            if (j < end) {
                const float* kr = Ksm + (j - w_lo) * KSTR + h * HD;
#pragma unroll
                for (int d = 0; d < 16; d++) {
                    float4 kv = *(const float4*)(kr + d * 4);
                    a += kv.x * qv[d].x;
                    a += kv.y * qv[d].y;
                    a += kv.z * qv[d].z;
                    a += kv.w * qv[d].w;
                }
                a *= 0.25f;   // / sqrt(64) / tau(0.5)
            }
            sc[q][h] = a;
        }
    }

    // per-head softmax over all 128 slots (padding slots hold score 0),
    // accumulate per-slot mean over heads
    float attn[4] = {0.f, 0.f, 0.f, 0.f};
#pragma unroll
    for (int h = 0; h < NHEAD; h++) {
        float mx = fmaxf(fmaxf(sc[0][h], sc[1][h]), fmaxf(sc[2][h], sc[3][h]));
#pragma unroll
        for (int o = 16; o > 0; o >>= 1)
            mx = fmaxf(mx, __shfl_xor_sync(0xffffffffu, mx, o));
        float e[4], s = 0.f;
#pragma unroll
        for (int q = 0; q < 4; q++) { e[q] = expf(sc[q][h] - mx); s += e[q]; }
#pragma unroll
        for (int o = 16; o > 0; o >>= 1)
            s += __shfl_xor_sync(0xffffffffu, s, o);
#pragma unroll
        for (int q = 0; q < 4; q++) attn[q] += e[q] / s;
    }

    // top-32 among VALID slots (invalid slots hold 0 in the output row and
    // all valid attn values are > 0, and L >= 64 > 32)
    float v[4];
#pragma unroll
    for (int q = 0; q < 4; q++) {
        int j = start + q * 32 + lane;
        v[q] = (j < end) ? attn[q] * 0.25f : -1.f;
    }

    const size_t rowbase = (size_t)i * NN;
    for (int it = 0; it < TOPK; it++) {
        // local argmax (lowest q, i.e. lowest m, wins ties)
        float bv = v[0];
        int bq_ = 0;
#pragma unroll
        for (int q = 1; q < 4; q++)
            if (v[q] > bv) { bv = v[q]; bq_ = q; }
        int bm = bq_ * 32 + lane;
        // warp argmax, ties -> smaller m (matches jax top_k stability)
#pragma unroll
        for (int o = 16; o > 0; o >>= 1) {
            float ov = __shfl_xor_sync(0xffffffffu, bv, o);
            int   om = __shfl_xor_sync(0xffffffffu, bm, o);
            if (ov > bv || (ov == bv && om < bm)) { bv = ov; bm = om; }
        }
        if ((bm & 31) == lane) v[bm >> 5] = -2.f;   // remove winner
        if (lane == 0) out[rowbase + start + bm] = 1.0f;
    }
}

// ---------------------------------------------------------------------------
extern "C" void kernel_launch(void* const* d_in, const int* in_sizes, int n_in,
                              void* d_out, int out_size)
{
    (void)in_sizes; (void)n_in; (void)out_size;
    const float* X  = (const float*)d_in[0];
    const float* Wq = (const float*)d_in[1];
    const float* bq = (const float*)d_in[2];
    const float* Wk = (const float*)d_in[3];
    const float* bk = (const float*)d_in[4];
    float* out = (float*)d_out;

    // 1) zero the 4096x4096 output
    zero_out_kernel<<<4096, 256>>>((float4*)out, (NN * NN) / 4);

    // 2) Q||K projection GEMM
    dim3 ggrid(512 / 128, NN / 128);
    gemm_qk_kernel<<<ggrid, 256>>>(X, Wq, bq, Wk, bk);

    // 3) attention + top-32 scatter
    const int smem_bytes = (MAXROWS * KSTR + NODES_PER_BLK * 256) * (int)sizeof(float);
    cudaFuncSetAttribute(attn_topk_kernel,
                         cudaFuncAttributeMaxDynamicSharedMemorySize, smem_bytes);
    attn_topk_kernel<<<NN / NODES_PER_BLK, 256, smem_bytes>>>(out);
}

// round 4
// speedup vs baseline: 1.2648x; 1.2648x over previous
#include <cuda_runtime.h>
#include <math.h>

// Problem constants (fixed by setup_inputs)
#define NN    4096
#define INF_  256
#define SEG   512
#define HALF  64
#define WIN   128
#define NHEAD 4
#define HD    64
#define TOPK  32

// attention kernel tiling
#define NODES_PER_BLK 8
#define MAXROWS 136          // union window rows: (NODES_PER_BLK-1) + 128 = 135, pad to 136
#define KSTR 260             // K smem row stride (floats); conflict-free per quarter-warp LDS.128

// scratch: Q||K projections, [4096][512]  (cols 0..255 = Q, 256..511 = K)
__device__ float g_QK[(size_t)NN * 512];

// ---------------------------------------------------------------------------
// packed fp32x2 helpers (sm_100+: fma.rn.f32x2 — 2 IEEE fp32 FMAs per issue)
// ---------------------------------------------------------------------------
__device__ __forceinline__ unsigned long long pk2(float x, float y) {
    unsigned long long r;
    asm("mov.b64 %0, {%1, %2};" : "=l"(r) : "f"(x), "f"(y));
    return r;
}
__device__ __forceinline__ void upk2(float& x, float& y, unsigned long long r) {
    asm("mov.b64 {%0, %1}, %2;" : "=f"(x), "=f"(y) : "l"(r));
}
__device__ __forceinline__ unsigned long long fma2(unsigned long long a,
                                                   unsigned long long b,
                                                   unsigned long long c) {
    unsigned long long d;
    asm("fma.rn.f32x2 %0, %1, %2, %3;" : "=l"(d) : "l"(a), "l"(b), "l"(c));
    return d;
}

// ---------------------------------------------------------------------------
// fused Q||K projection GEMM:  C[4096,512] = X[4096,256] @ [Wq|Wk] + [bq|bk]
// BM=128, BN=128, BK=16, 256 threads, 8x8 per thread, f32x2 inner.
// Also zero-fills 32 rows (512 KB) of the output matrix per block — the
// stores drain behind the FFMA-bound mainloop.
// ---------------------------------------------------------------------------
__global__ __launch_bounds__(256) void gemm_qk_kernel(
    const float* __restrict__ X,
    const float* __restrict__ Wq, const float* __restrict__ bq,
    const float* __restrict__ Wk, const float* __restrict__ bk,
    float4* __restrict__ out4)
{
    __shared__ float As[16][128];   // transposed A tile
    __shared__ float Bs[16][128];

    const int tid  = threadIdx.x;
    const int brow = blockIdx.y * 128;
    const int bcol = blockIdx.x * 128;

    // ---- zero-fill slice of the output: block zb covers rows [zb*32, zb*32+32)
    {
        const int zb = blockIdx.y * gridDim.x + blockIdx.x;   // 0..127
        float4* zdst = out4 + (size_t)zb * (32 * NN / 4);
        const float4 z = make_float4(0.f, 0.f, 0.f, 0.f);
#pragma unroll
        for (int t = 0; t < (32 * NN / 4) / 256; t++)
            zdst[t * 256 + tid] = z;
    }

    // each block lies entirely in the Q half (bcol<256) or K half
    const float* W    = (bcol < 256) ? Wq : Wk;
    const float* bias = (bcol < 256) ? bq : bk;
    const int wcol = bcol & 255;

    const int tx = tid & 15;
    const int ty = tid >> 4;

    unsigned long long acc2[8][4];
#pragma unroll
    for (int a = 0; a < 8; a++)
#pragma unroll
        for (int b = 0; b < 4; b++) acc2[a][b] = 0ULL;

    for (int k0 = 0; k0 < INF_; k0 += 16) {
        // load A tile 128x16 (512 float4, 2 per thread), transpose into As[k][m]
#pragma unroll
        for (int t = 0; t < 2; t++) {
            int f = tid + t * 256;
            int r = f >> 2;
            int c = (f & 3) << 2;
            float4 v = *(const float4*)(X + (size_t)(brow + r) * INF_ + k0 + c);
            As[c + 0][r] = v.x;
            As[c + 1][r] = v.y;
            As[c + 2][r] = v.z;
            As[c + 3][r] = v.w;
        }
        // load B tile 16x128 (row-major copy)
#pragma unroll
        for (int t = 0; t < 2; t++) {
            int f = tid + t * 256;
            int r = f >> 5;
            int c = (f & 31) << 2;
            *(float4*)&Bs[r][c] =
                *(const float4*)(W + (size_t)(k0 + r) * 256 + wcol + c);
        }
        __syncthreads();

#pragma unroll
        for (int k = 0; k < 16; k++) {
            float a[8], b[8];
            *(float4*)&a[0] = *(float4*)&As[k][ty * 8];
            *(float4*)&a[4] = *(float4*)&As[k][ty * 8 + 4];
            *(float4*)&b[0] = *(float4*)&Bs[k][tx * 8];
            *(float4*)&b[4] = *(float4*)&Bs[k][tx * 8 + 4];
            unsigned long long b2[4];
            b2[0] = pk2(b[0], b[1]);
            b2[1] = pk2(b[2], b[3]);
            b2[2] = pk2(b[4], b[5]);
            b2[3] = pk2(b[6], b[7]);
#pragma unroll
            for (int ii = 0; ii < 8; ii++) {
                unsigned long long a2 = pk2(a[ii], a[ii]);
#pragma unroll
                for (int jp = 0; jp < 4; jp++)
                    acc2[ii][jp] = fma2(a2, b2[jp], acc2[ii][jp]);
            }
        }
        __syncthreads();
    }

    // epilogue: unpack, +bias, store
#pragma unroll
    for (int ii = 0; ii < 8; ii++) {
        int r = brow + ty * 8 + ii;
        float c[8];
#pragma unroll
        for (int jp = 0; jp < 4; jp++)
            upk2(c[2 * jp], c[2 * jp + 1], acc2[ii][jp]);
#pragma unroll
        for (int jj = 0; jj < 8; jj += 4) {
            int cl = tx * 8 + jj;
            float4 v;
            v.x = c[jj + 0] + bias[wcol + cl + 0];
            v.y = c[jj + 1] + bias[wcol + cl + 1];
            v.z = c[jj + 2] + bias[wcol + cl + 2];
            v.w = c[jj + 3] + bias[wcol + cl + 3];
            *(float4*)(g_QK + (size_t)r * 512 + bcol + cl) = v;
        }
    }
}

// ---------------------------------------------------------------------------
// windowed attention + softmax (zero-padding included in the denominator, as
// the reference does) + exact top-32 selection + parallel scatter of 1.0f.
// One warp per node, 8 nodes per block, K window union staged in smem.
// ---------------------------------------------------------------------------
__global__ __launch_bounds__(256) void attn_topk_kernel(float* __restrict__ out)
{
    extern __shared__ float smem[];
    float* Ksm = smem;                       // [MAXROWS][KSTR]
    float* Qsm = smem + MAXROWS * KSTR;      // [8][256]

    const int i0   = blockIdx.x * NODES_PER_BLK;
    const int s0   = i0 & ~(SEG - 1);
    const int e0   = s0 + SEG;
    const int w_lo = max(s0, i0 - HALF);
    const int w_hi = min(e0, i0 + (NODES_PER_BLK - 1) + HALF);
    const int rows = w_hi - w_lo;            // <= 135

    // stage K rows [w_lo, w_hi)
    for (int idx = threadIdx.x; idx < rows * 64; idx += 256) {
        int r = idx >> 6;
        int c = (idx & 63) << 2;
        *(float4*)(Ksm + r * KSTR + c) =
            *(const float4*)(g_QK + (size_t)(w_lo + r) * 512 + 256 + c);
    }
    // stage Q rows i0..i0+7
    for (int idx = threadIdx.x; idx < NODES_PER_BLK * 64; idx += 256) {
        int r = idx >> 6;
        int c = (idx & 63) << 2;
        *(float4*)(Qsm + r * 256 + c) =
            *(const float4*)(g_QK + (size_t)(i0 + r) * 512 + c);
    }
    __syncthreads();

    const int w    = threadIdx.x >> 5;
    const int lane = threadIdx.x & 31;
    const int i    = i0 + w;
    const int start = max(s0, i - HALF);
    const int end   = min(e0, i + HALF);     // exclusive; valid count in [65,128]

    // per-head: scores for slot m = q*32 + lane (invalid -> exactly 0, which
    // the reference keeps in the softmax), softmax WITHOUT max subtraction
    // (|score| <~ 12, exp is safe), accumulate head-mean attention per slot.
    float attn[4] = {0.f, 0.f, 0.f, 0.f};
#pragma unroll
    for (int h = 0; h < NHEAD; h++) {
        // pack this node's head-h query into f32x2 registers
        unsigned long long q2[32];
#pragma unroll
        for (int d = 0; d < 16; d++) {
            float4 qv = *(const float4*)(Qsm + w * 256 + h * HD + d * 4);
            q2[2 * d]     = pk2(qv.x, qv.y);
            q2[2 * d + 1] = pk2(qv.z, qv.w);
        }
        float e[4];
        float s = 0.f;
#pragma unroll
        for (int q = 0; q < 4; q++) {
            int j = start + q * 32 + lane;
            float a = 0.f;
            if (j < end) {
                const float* kr = Ksm + (j - w_lo) * KSTR + h * HD;
                unsigned long long acc2 = 0ULL;
#pragma unroll
                for (int d = 0; d < 16; d++) {
                    float4 kv = *(const float4*)(kr + d * 4);
                    acc2 = fma2(pk2(kv.x, kv.y), q2[2 * d],     acc2);
                    acc2 = fma2(pk2(kv.z, kv.w), q2[2 * d + 1], acc2);
                }
                float lo, hi;
                upk2(lo, hi, acc2);
                a = (lo + hi) * 0.25f;       // / sqrt(64) / tau(0.5)
            }
            e[q] = __expf(a);                // a==0 -> exactly 1 (padding slots)
            s += e[q];
        }
#pragma unroll
        for (int o = 16; o > 0; o >>= 1)
            s += __shfl_xor_sync(0xffffffffu, s, o);
        float rs = __fdividef(1.f, s);
#pragma unroll
        for (int q = 0; q < 4; q++) attn[q] += e[q] * rs;
    }

    // ---- exact top-32 selection ------------------------------------------
    // keys: valid slots have attn > 0, so raw float bits are order-isomorphic
    // as u32; invalid slots get key 0. attn*0.25 <= 1.0 -> bits 31,30 are 0.
    unsigned u[4];
#pragma unroll
    for (int q = 0; q < 4; q++) {
        int j = start + q * 32 + lane;
        u[q] = (j < end) ? __float_as_uint(attn[q] * 0.25f) : 0u;
    }

    // radix descent: find T = 32nd-largest key (exact)
    unsigned T = 0;
#pragma unroll 1
    for (int bit = 29; bit >= 0; --bit) {
        unsigned cand = T | (1u << bit);
        int c = (u[0] >= cand) + (u[1] >= cand) + (u[2] >= cand) + (u[3] >= cand);
        c = __reduce_add_sync(0xffffffffu, c);
        if (c >= TOPK) T = cand;
    }

    // select: everything > T, plus ties == T filled in ascending slot order
    // (matches jax.lax.top_k's smaller-index-first tie rule)
    int gt = (u[0] > T) + (u[1] > T) + (u[2] > T) + (u[3] > T);
    int rem = TOPK - __reduce_add_sync(0xffffffffu, gt);

    const size_t rowbase = (size_t)i * NN + start;
#pragma unroll
    for (int q = 0; q < 4; q++) {
        bool eq = (u[q] == T);
        unsigned meq = __ballot_sync(0xffffffffu, eq);
        int before = __popc(meq & ((1u << lane) - 1u));
        bool sel = (u[q] > T) || (eq && before < rem);
        if (sel) out[rowbase + q * 32 + lane] = 1.0f;
        int tk = __popc(meq);
        rem -= (tk < rem) ? tk : rem;
    }
}

// ---------------------------------------------------------------------------
extern "C" void kernel_launch(void* const* d_in, const int* in_sizes, int n_in,
                              void* d_out, int out_size)
{
    (void)in_sizes; (void)n_in; (void)out_size;
    const float* X  = (const float*)d_in[0];
    const float* Wq = (const float*)d_in[1];
    const float* bq = (const float*)d_in[2];
    const float* Wk = (const float*)d_in[3];
    const float* bk = (const float*)d_in[4];
    float* out = (float*)d_out;

    // 1) Q||K projection GEMM + zero-fill of the 4096x4096 output
    dim3 ggrid(512 / 128, NN / 128);
    gemm_qk_kernel<<<ggrid, 256>>>(X, Wq, bq, Wk, bk, (float4*)out);

    // 2) attention + exact top-32 scatter
    const int smem_bytes = (MAXROWS * KSTR + NODES_PER_BLK * 256) * (int)sizeof(float);
    cudaFuncSetAttribute(attn_topk_kernel,
                         cudaFuncAttributeMaxDynamicSharedMemorySize, smem_bytes);
    attn_topk_kernel<<<NN / NODES_PER_BLK, 256, smem_bytes>>>(out);
}

// round 6
// speedup vs baseline: 1.6279x; 1.2871x over previous
#include <cuda_runtime.h>
#include <math.h>

// Problem constants (fixed by setup_inputs)
#define NN    4096
#define INF_  256
#define SEG   512
#define HALF  64
#define WIN   128
#define NHEAD 4
#define HD    64
#define TOPK  32

// attention kernel tiling
#define NPB   32             // nodes per block
#define ATHR  1024           // attention threads per block (32 warps)
#define MAXR  160            // union window rows: (NPB-1)+128 = 159, pad to 160
#define KSTR  260            // K smem row stride (floats); conflict-free LDS.128

// GEMM tiling
#define GBM 64
#define GBN 64
#define GBK 16
#define GTHR 128
#define ASTR 68              // padded smem stride (68*4 bytes, 16B-aligned, low conflict)

// scratch: Q||K projections, [4096][512]  (cols 0..255 = Q, 256..511 = K)
__device__ float g_QK[(size_t)NN * 512];

// ---------------------------------------------------------------------------
// packed fp32x2 helpers (sm_100+: fma.rn.f32x2 — 2 IEEE fp32 FMAs per issue)
// ---------------------------------------------------------------------------
__device__ __forceinline__ unsigned long long pk2(float x, float y) {
    unsigned long long r;
    asm("mov.b64 %0, {%1, %2};" : "=l"(r) : "f"(x), "f"(y));
    return r;
}
__device__ __forceinline__ void upk2(float& x, float& y, unsigned long long r) {
    asm("mov.b64 {%0, %1}, %2;" : "=f"(x), "=f"(y) : "l"(r));
}
__device__ __forceinline__ unsigned long long fma2(unsigned long long a,
                                                   unsigned long long b,
                                                   unsigned long long c) {
    unsigned long long d;
    asm("fma.rn.f32x2 %0, %1, %2, %3;" : "=l"(d) : "l"(a), "l"(b), "l"(c));
    return d;
}

// ---------------------------------------------------------------------------
// fused Q||K projection GEMM:  C[4096,512] = X[4096,256] @ [Wq|Wk] + [bq|bk]
// BM=64, BN=64, BK=16, 128 threads, 8x4 per thread (f32x2 pairs along M).
// grid = (8, 64) = 512 blocks -> single wave, high occupancy.
// Each block also zero-fills 128 KB (8 rows) of the output matrix.
// ---------------------------------------------------------------------------
__global__ __launch_bounds__(GTHR) void gemm_qk_kernel(
    const float* __restrict__ X,
    const float* __restrict__ Wq, const float* __restrict__ bq,
    const float* __restrict__ Wk, const float* __restrict__ bk,
    float4* __restrict__ out4)
{
    __shared__ float As[GBK][ASTR];   // transposed A tile [k][m]
    __shared__ float Bs[GBK][ASTR];   // B tile [k][n]

    const int tid = threadIdx.x;

    // ---- zero-fill slice of the output: block zb covers 8 rows (128 KB)
    {
        const int zb = blockIdx.y * gridDim.x + blockIdx.x;   // 0..511
        float4* zdst = out4 + (size_t)zb * (8 * NN / 4);
        const float4 z = make_float4(0.f, 0.f, 0.f, 0.f);
#pragma unroll
        for (int t = 0; t < (8 * NN / 4) / GTHR; t++)
            zdst[t * GTHR + tid] = z;
    }

    const int brow = blockIdx.y * GBM;
    const int bcol = blockIdx.x * GBN;

    // each block lies entirely in the Q half (bcol<256) or K half
    const float* W    = (bcol < 256) ? Wq : Wk;
    const float* bias = (bcol < 256) ? bq : bk;
    const int wcol = bcol & 255;

    const int tx = tid & 15;          // n0 = tx*4
    const int ty = tid >> 4;          // m0 = ty*8
    const int m0 = ty * 8;
    const int n0 = tx * 4;

    unsigned long long acc2[4][4];    // [m-pair][n]
#pragma unroll
    for (int a = 0; a < 4; a++)
#pragma unroll
        for (int b = 0; b < 4; b++) acc2[a][b] = 0ULL;

    for (int k0 = 0; k0 < INF_; k0 += GBK) {
        // load A tile 64x16 (256 float4, 2 per thread), transpose into As[k][m]
#pragma unroll
        for (int t = 0; t < 2; t++) {
            int f = tid + t * GTHR;
            int r = f >> 2;
            int c = (f & 3) << 2;
            float4 v = *(const float4*)(X + (size_t)(brow + r) * INF_ + k0 + c);
            As[c + 0][r] = v.x;
            As[c + 1][r] = v.y;
            As[c + 2][r] = v.z;
            As[c + 3][r] = v.w;
        }
        // load B tile 16x64 (row-major copy)
#pragma unroll
        for (int t = 0; t < 2; t++) {
            int f = tid + t * GTHR;
            int r = f >> 4;
            int c = (f & 15) << 2;
            *(float4*)&Bs[r][c] =
                *(const float4*)(W + (size_t)(k0 + r) * 256 + wcol + c);
        }
        __syncthreads();

#pragma unroll
        for (int k = 0; k < GBK; k++) {
            float a[8], b[4];
            *(float4*)&a[0] = *(float4*)&As[k][m0];
            *(float4*)&a[4] = *(float4*)&As[k][m0 + 4];
            *(float4*)&b[0] = *(float4*)&Bs[k][n0];
            unsigned long long a2[4];
            a2[0] = pk2(a[0], a[1]);
            a2[1] = pk2(a[2], a[3]);
            a2[2] = pk2(a[4], a[5]);
            a2[3] = pk2(a[6], a[7]);
            unsigned long long bd[4];
            bd[0] = pk2(b[0], b[0]);
            bd[1] = pk2(b[1], b[1]);
            bd[2] = pk2(b[2], b[2]);
            bd[3] = pk2(b[3], b[3]);
#pragma unroll
            for (int mp = 0; mp < 4; mp++)
#pragma unroll
                for (int n = 0; n < 4; n++)
                    acc2[mp][n] = fma2(a2[mp], bd[n], acc2[mp][n]);
        }
        __syncthreads();
    }

    // epilogue: unpack, +bias, store two rows per m-pair
    float4 bv = *(const float4*)(bias + wcol + n0);
#pragma unroll
    for (int mp = 0; mp < 4; mp++) {
        float lo[4], hi[4];
#pragma unroll
        for (int n = 0; n < 4; n++) upk2(lo[n], hi[n], acc2[mp][n]);
        int r0 = brow + m0 + 2 * mp;
        float4 v0, v1;
        v0.x = lo[0] + bv.x; v0.y = lo[1] + bv.y; v0.z = lo[2] + bv.z; v0.w = lo[3] + bv.w;
        v1.x = hi[0] + bv.x; v1.y = hi[1] + bv.y; v1.z = hi[2] + bv.z; v1.w = hi[3] + bv.w;
        *(float4*)(g_QK + (size_t)r0 * 512 + bcol + n0) = v0;
        *(float4*)(g_QK + (size_t)(r0 + 1) * 512 + bcol + n0) = v1;
    }
}

// ---------------------------------------------------------------------------
// windowed attention + softmax (zero-padding included in the denominator, as
// the reference does) + exact top-32 selection + parallel scatter of 1.0f.
// One warp per node, 32 nodes per block (1024 threads = 32 warps/SM).
// Invalid window slots use clamped row pointers (uniform control flow) and
// are masked out with a select before exp.
// ---------------------------------------------------------------------------
__global__ __launch_bounds__(ATHR) void attn_topk_kernel(float* __restrict__ out)
{
    extern __shared__ float smem[];
    float* Ksm = smem;                       // [MAXR][KSTR]
    float* Qsm = smem + MAXR * KSTR;         // [NPB][256]

    const int i0   = blockIdx.x * NPB;
    const int s0   = i0 & ~(SEG - 1);
    const int e0   = s0 + SEG;
    const int w_lo = max(s0, i0 - HALF);
    const int w_hi = min(e0, i0 + (NPB - 1) + HALF);
    const int rows = w_hi - w_lo;            // <= 159

    // stage K rows [w_lo, w_hi)
    for (int idx = threadIdx.x; idx < rows * 64; idx += ATHR) {
        int r = idx >> 6;
        int c = (idx & 63) << 2;
        *(float4*)(Ksm + r * KSTR + c) =
            *(const float4*)(g_QK + (size_t)(w_lo + r) * 512 + 256 + c);
    }
    // stage Q rows i0..i0+31
    for (int idx = threadIdx.x; idx < NPB * 64; idx += ATHR) {
        int r = idx >> 6;
        int c = (idx & 63) << 2;
        *(float4*)(Qsm + r * 256 + c) =
            *(const float4*)(g_QK + (size_t)(i0 + r) * 512 + c);
    }
    __syncthreads();

    const int w    = threadIdx.x >> 5;
    const int lane = threadIdx.x & 31;
    const int i    = i0 + w;
    const int start = max(s0, i - HALF);
    const int end   = min(e0, i + HALF);     // exclusive; valid count in [65,128]

    // clamped smem row offsets; invalid slots point at a real (valid) row and
    // their contribution is masked before exp.
    int roff[4];
    bool val[4];
#pragma unroll
    for (int q = 0; q < 4; q++) {
        int j = start + q * 32 + lane;
        val[q] = (j < end);
        int jc = val[q] ? j : (end - 1);
        roff[q] = (jc - w_lo) * KSTR;
    }

    float attn[4] = {0.f, 0.f, 0.f, 0.f};
#pragma unroll
    for (int h = 0; h < NHEAD; h++) {
        unsigned long long acc[4] = {0ULL, 0ULL, 0ULL, 0ULL};
        const float* qb = Qsm + w * 256 + h * HD;
#pragma unroll
        for (int d = 0; d < 16; d++) {
            float4 qv = *(const float4*)(qb + d * 4);          // warp broadcast
            unsigned long long qlo = pk2(qv.x, qv.y);
            unsigned long long qhi = pk2(qv.z, qv.w);
#pragma unroll
            for (int q = 0; q < 4; q++) {
                float4 kv = *(const float4*)(Ksm + roff[q] + h * HD + d * 4);
                acc[q] = fma2(pk2(kv.x, kv.y), qlo, acc[q]);
                acc[q] = fma2(pk2(kv.z, kv.w), qhi, acc[q]);
            }
        }
        float e[4];
        float s = 0.f;
#pragma unroll
        for (int q = 0; q < 4; q++) {
            float lo, hi;
            upk2(lo, hi, acc[q]);
            float a = val[q] ? (lo + hi) * 0.25f : 0.f;  // /sqrt(64)/tau; pad->0
            e[q] = __expf(a);                            // pad slots -> exactly 1
            s += e[q];
        }
#pragma unroll
        for (int o = 16; o > 0; o >>= 1)
            s += __shfl_xor_sync(0xffffffffu, s, o);
        float rs = __fdividef(1.f, s);
#pragma unroll
        for (int q = 0; q < 4; q++) attn[q] += e[q] * rs;
    }

    // ---- exact top-32 selection ------------------------------------------
    // keys: valid slots have attn > 0, so raw float bits are order-isomorphic
    // as u32; invalid slots get key 0. attn*0.25 <= 1.0 -> bits 31,30 are 0.
    unsigned u[4];
#pragma unroll
    for (int q = 0; q < 4; q++)
        u[q] = val[q] ? __float_as_uint(attn[q] * 0.25f) : 0u;

    // radix descent: find T = 32nd-largest key (exact)
    unsigned T = 0;
#pragma unroll 1
    for (int bit = 29; bit >= 0; --bit) {
        unsigned cand = T | (1u << bit);
        int c = (u[0] >= cand) + (u[1] >= cand) + (u[2] >= cand) + (u[3] >= cand);
        c = __reduce_add_sync(0xffffffffu, c);
        if (c >= TOPK) T = cand;
    }

    // select: everything > T, plus ties == T filled in ascending slot order
    // (matches jax.lax.top_k's smaller-index-first tie rule)
    int gt = (u[0] > T) + (u[1] > T) + (u[2] > T) + (u[3] > T);
    int rem = TOPK - __reduce_add_sync(0xffffffffu, gt);

    const size_t rowbase = (size_t)i * NN + start;
#pragma unroll
    for (int q = 0; q < 4; q++) {
        bool eq = (u[q] == T);
        unsigned meq = __ballot_sync(0xffffffffu, eq);
        int before = __popc(meq & ((1u << lane) - 1u));
        bool sel = (u[q] > T) || (eq && before < rem);
        if (sel) out[rowbase + q * 32 + lane] = 1.0f;
        int tk = __popc(meq);
        rem -= (tk < rem) ? tk : rem;
    }
}

// ---------------------------------------------------------------------------
extern "C" void kernel_launch(void* const* d_in, const int* in_sizes, int n_in,
                              void* d_out, int out_size)
{
    (void)in_sizes; (void)n_in; (void)out_size;
    const float* X  = (const float*)d_in[0];
    const float* Wq = (const float*)d_in[1];
    const float* bq = (const float*)d_in[2];
    const float* Wk = (const float*)d_in[3];
    const float* bk = (const float*)d_in[4];
    float* out = (float*)d_out;

    // 1) Q||K projection GEMM + zero-fill of the 4096x4096 output
    dim3 ggrid(512 / GBN, NN / GBM);          // (8, 64) = 512 blocks
    gemm_qk_kernel<<<ggrid, GTHR>>>(X, Wq, bq, Wk, bk, (float4*)out);

    // 2) attention + exact top-32 scatter (32 warps/SM, single wave)
    const int smem_bytes = (MAXR * KSTR + NPB * 256) * (int)sizeof(float);
    cudaFuncSetAttribute(attn_topk_kernel,
                         cudaFuncAttributeMaxDynamicSharedMemorySize, smem_bytes);
    attn_topk_kernel<<<NN / NPB, ATHR, smem_bytes>>>(out);
}